// round 12
// baseline (speedup 1.0000x reference)
#include <cuda_runtime.h>
#include <math.h>

#define BB 32
#define HH 32
#define KVHH 8
#define DD 128
#define GG 4
#define BLK_SZ 16
#define MAX_BLOCKS 128
#define NSPLIT 8
#define NWARP 8
#define NTHREADS 256

// Scratch (allocation-free: __device__ globals)
__device__ float g_pacc[BB * KVHH * NSPLIT * GG * DD];  // 4 MB split partials
__device__ float g_pl[BB * KVHH * NSPLIT * GG];
__device__ float g_qrot[BB * HH * DD];    // RoPE'd q, scale folded
__device__ float g_krot[BB * KVHH * DD];  // RoPE'd new k

// ---------------- prep: RoPE q and new-k once (R7-proven) ----------------
__global__ __launch_bounds__(DD) void rope_prep_kernel(
    const float* __restrict__ query,
    const float* __restrict__ key,
    const int*   __restrict__ context_lens)
{
    const int b = blockIdx.x;
    const int h = blockIdx.y;   // 0..HH-1 q head, HH..HH+KVHH-1 k head
    const int d = threadIdx.x;

    const float pos = (float)context_lens[b];
    const int fi = d & 63;
    const float inv = exp2f(-(float)fi * 0.2076205092783674f);  // log2(10000)/64
    float s, c;
    sincosf(pos * inv, &s, &c);

    if (h < HH) {
        const float* base = query + ((long)b * HH + h) * DD;
        float x = base[d];
        float other = (d < 64) ? -base[d + 64] : base[d - 64];
        g_qrot[((long)b * HH + h) * DD + d] =
            (x * c + other * s) * 0.08838834764831845f;  // D^-0.5
    } else {
        const int kh = h - HH;
        const float* base = key + ((long)b * KVHH + kh) * DD;
        float x = base[d];
        float other = (d < 64) ? -base[d + 64] : base[d - 64];
        g_krot[((long)b * KVHH + kh) * DD + d] = x * c + other * s;
    }
}

// ------- per-token update (R7-proven): no online max, butterfly reduce -------
__device__ __forceinline__ void upd_token(
    const float4& kv, const float4& vv,
    const float4 qv[GG], float l[GG], float4 acc[GG])
{
    float sc[GG];
#pragma unroll
    for (int g = 0; g < GG; g++)
        sc[g] = kv.x * qv[g].x + kv.y * qv[g].y + kv.z * qv[g].z + kv.w * qv[g].w;
#pragma unroll
    for (int off = 16; off > 0; off >>= 1) {
#pragma unroll
        for (int g = 0; g < GG; g++)
            sc[g] += __shfl_xor_sync(0xffffffffu, sc[g], off);
    }
#pragma unroll
    for (int g = 0; g < GG; g++) {
        float p = __expf(sc[g]);
        l[g] += p;
        acc[g].x += p * vv.x;
        acc[g].y += p * vv.y;
        acc[g].z += p * vv.z;
        acc[g].w += p * vv.w;
    }
}

// ---------------- split flash-decode (R7 skeleton, 8x load batch) ----------------
__global__ __launch_bounds__(NTHREADS) void pa_split_kernel(
    const float* __restrict__ value,
    const float* __restrict__ k_cache,
    const float* __restrict__ v_cache,
    const int*   __restrict__ block_table,
    const int*   __restrict__ context_lens)
{
    const int split = blockIdx.x;
    const int kvh   = blockIdx.y;
    const int b     = blockIdx.z;
    const int tid   = threadIdx.x;
    const int lane  = tid & 31;
    const int w     = tid >> 5;

    const int ctx   = context_lens[b];
    const int chunk = (ctx + NSPLIT - 1) / NSPLIT;
    const int s0    = split * chunk;
    const int s1    = min(s0 + chunk, ctx);
    const int last  = ctx - 1;
    const int end   = min(s1, last);   // hot loop excludes the in-flight token

    __shared__ int   btab[MAX_BLOCKS];
    __shared__ float wl[NWARP][GG];
    __shared__ float wacc[NWARP][GG][DD];

    for (int i = tid; i < MAX_BLOCKS; i += NTHREADS)
        btab[i] = block_table[b * MAX_BLOCKS + i];
    __syncthreads();

    float4 qv[GG];
#pragma unroll
    for (int g = 0; g < GG; g++)
        qv[g] = *(const float4*)&g_qrot[((long)b * HH + kvh * GG + g) * DD + lane * 4];

    float l[GG];
    float4 acc[GG];
#pragma unroll
    for (int g = 0; g < GG; g++) {
        l[g] = 0.f;
        acc[g].x = acc[g].y = acc[g].z = acc[g].w = 0.f;
    }

    const unsigned hoff = (unsigned)kvh * DD + lane * 4;
#define TOKOFF(t) ((((unsigned)btab[(t) >> 4] * BLK_SZ + ((t) & 15)) * (KVHH * DD)) + hoff)

    int s = s0 + w;
    // 8x unrolled: 16 LDG.128 in flight per warp before any compute
    while (s + 7 * NWARP < end) {
        unsigned o0 = TOKOFF(s);
        unsigned o1 = TOKOFF(s + NWARP);
        unsigned o2 = TOKOFF(s + 2 * NWARP);
        unsigned o3 = TOKOFF(s + 3 * NWARP);
        unsigned o4 = TOKOFF(s + 4 * NWARP);
        unsigned o5 = TOKOFF(s + 5 * NWARP);
        unsigned o6 = TOKOFF(s + 6 * NWARP);
        unsigned o7 = TOKOFF(s + 7 * NWARP);

        float4 k0 = *(const float4*)(k_cache + o0);
        float4 v0 = *(const float4*)(v_cache + o0);
        float4 k1 = *(const float4*)(k_cache + o1);
        float4 v1 = *(const float4*)(v_cache + o1);
        float4 k2 = *(const float4*)(k_cache + o2);
        float4 v2 = *(const float4*)(v_cache + o2);
        float4 k3 = *(const float4*)(k_cache + o3);
        float4 v3 = *(const float4*)(v_cache + o3);
        float4 k4 = *(const float4*)(k_cache + o4);
        float4 v4 = *(const float4*)(v_cache + o4);
        float4 k5 = *(const float4*)(k_cache + o5);
        float4 v5 = *(const float4*)(v_cache + o5);
        float4 k6 = *(const float4*)(k_cache + o6);
        float4 v6 = *(const float4*)(v_cache + o6);
        float4 k7 = *(const float4*)(k_cache + o7);
        float4 v7 = *(const float4*)(v_cache + o7);

        upd_token(k0, v0, qv, l, acc);
        upd_token(k1, v1, qv, l, acc);
        upd_token(k2, v2, qv, l, acc);
        upd_token(k3, v3, qv, l, acc);
        upd_token(k4, v4, qv, l, acc);
        upd_token(k5, v5, qv, l, acc);
        upd_token(k6, v6, qv, l, acc);
        upd_token(k7, v7, qv, l, acc);
        s += 8 * NWARP;
    }
    // 4x tail
    while (s + 3 * NWARP < end) {
        unsigned o0 = TOKOFF(s);
        unsigned o1 = TOKOFF(s + NWARP);
        unsigned o2 = TOKOFF(s + 2 * NWARP);
        unsigned o3 = TOKOFF(s + 3 * NWARP);
        float4 k0 = *(const float4*)(k_cache + o0);
        float4 v0 = *(const float4*)(v_cache + o0);
        float4 k1 = *(const float4*)(k_cache + o1);
        float4 v1 = *(const float4*)(v_cache + o1);
        float4 k2 = *(const float4*)(k_cache + o2);
        float4 v2 = *(const float4*)(v_cache + o2);
        float4 k3 = *(const float4*)(k_cache + o3);
        float4 v3 = *(const float4*)(v_cache + o3);
        upd_token(k0, v0, qv, l, acc);
        upd_token(k1, v1, qv, l, acc);
        upd_token(k2, v2, qv, l, acc);
        upd_token(k3, v3, qv, l, acc);
        s += 4 * NWARP;
    }
    while (s < end) {
        unsigned off = TOKOFF(s);
        float4 kv = *(const float4*)(k_cache + off);
        float4 vv = *(const float4*)(v_cache + off);
        upd_token(kv, vv, qv, l, acc);
        s += NWARP;
    }
#undef TOKOFF

    // in-flight token (RoPE'd new k from scratch, new v from input)
    if (last >= s0 && last < s1 && w == ((last - s0) % NWARP)) {
        float4 kv = *(const float4*)&g_krot[((long)b * KVHH + kvh) * DD + lane * 4];
        float4 vv = *(const float4*)(value + ((long)b * KVHH + kvh) * DD + lane * 4);
        upd_token(kv, vv, qv, l, acc);
    }

    // stash per-warp partials (plain sums)
#pragma unroll
    for (int g = 0; g < GG; g++) {
        if (lane == 0) wl[w][g] = l[g];
        *(float4*)&wacc[w][g][lane * 4] = acc[g];
    }
    __syncthreads();

    const long pbase = ((long)(b * KVHH + kvh) * NSPLIT + split) * GG;
    for (int i = tid; i < GG * DD; i += NTHREADS) {
        int g = i >> 7, d = i & 127;
        float t = 0.f;
#pragma unroll
        for (int ww = 0; ww < NWARP; ww++) t += wacc[ww][g][d];
        g_pacc[(pbase + g) * DD + d] = t;
    }
    if (tid < GG) {
        float L = 0.f;
#pragma unroll
        for (int ww = 0; ww < NWARP; ww++) L += wl[ww][tid];
        g_pl[pbase + tid] = L;
    }
}

// ---------------- combine (plain sums) ----------------
__global__ __launch_bounds__(DD) void pa_combine_kernel(float* __restrict__ out) {
    const int idx = blockIdx.x;             // B*KVH*G
    const int g   = idx % GG;
    const int kvh = (idx / GG) % KVHH;
    const int b   = idx / (GG * KVHH);
    const int d   = threadIdx.x;

    const long base = ((long)(b * KVHH + kvh) * NSPLIT) * GG + g;
    float L = 0.f, o = 0.f;
#pragma unroll
    for (int s = 0; s < NSPLIT; s++) {
        L += g_pl[base + (long)s * GG];
        o += g_pacc[(base + (long)s * GG) * DD + d];
    }
    out[((long)b * HH + kvh * GG + g) * DD + d] = o / L;
}

extern "C" void kernel_launch(void* const* d_in, const int* in_sizes, int n_in,
                              void* d_out, int out_size) {
    const float* query  = (const float*)d_in[0];
    const float* key    = (const float*)d_in[1];
    const float* value  = (const float*)d_in[2];
    const float* k_cache = (const float*)d_in[3];
    const float* v_cache = (const float*)d_in[4];
    const int*   block_table  = (const int*)d_in[5];
    const int*   context_lens = (const int*)d_in[6];
    float* out = (float*)d_out;

    dim3 pgrid(BB, HH + KVHH);
    rope_prep_kernel<<<pgrid, DD>>>(query, key, context_lens);

    dim3 grid(NSPLIT, KVHH, BB);
    pa_split_kernel<<<grid, NTHREADS>>>(value, k_cache, v_cache,
                                        block_table, context_lens);
    pa_combine_kernel<<<BB * KVHH * GG, DD>>>(out);
}

// round 13
// speedup vs baseline: 1.4062x; 1.4062x over previous
#include <cuda_runtime.h>
#include <math.h>

#define BB 32
#define HH 32
#define KVHH 8
#define DD 128
#define GG 4
#define BLK_SZ 16
#define MAX_BLOCKS 128
#define NSPLIT 8
#define NWARP 8
#define NTHREADS 256
#define KV_TILE 32          // tokens per smem stage
#define TOKF 256            // floats per token in smem (K 128 + V 128)

// Scratch (allocation-free: __device__ globals)
__device__ float g_pacc[BB * KVHH * NSPLIT * GG * DD];  // 4 MB split partials
__device__ float g_pl[BB * KVHH * NSPLIT * GG];
__device__ float g_qrot[BB * HH * DD];    // RoPE'd q, scale folded
__device__ float g_krot[BB * KVHH * DD];  // RoPE'd new k

// ---------------- prep: RoPE q and new-k once (R7-proven) ----------------
__global__ __launch_bounds__(DD) void rope_prep_kernel(
    const float* __restrict__ query,
    const float* __restrict__ key,
    const int*   __restrict__ context_lens)
{
    const int b = blockIdx.x;
    const int h = blockIdx.y;
    const int d = threadIdx.x;

    const float pos = (float)context_lens[b];
    const int fi = d & 63;
    const float inv = exp2f(-(float)fi * 0.2076205092783674f);  // log2(10000)/64
    float s, c;
    sincosf(pos * inv, &s, &c);

    if (h < HH) {
        const float* base = query + ((long)b * HH + h) * DD;
        float x = base[d];
        float other = (d < 64) ? -base[d + 64] : base[d - 64];
        g_qrot[((long)b * HH + h) * DD + d] =
            (x * c + other * s) * 0.08838834764831845f;  // D^-0.5
    } else {
        const int kh = h - HH;
        const float* base = key + ((long)b * KVHH + kh) * DD;
        float x = base[d];
        float other = (d < 64) ? -base[d + 64] : base[d - 64];
        g_krot[((long)b * KVHH + kh) * DD + d] = x * c + other * s;
    }
}

// ------- per-token update (R7-proven): no online max, butterfly reduce -------
__device__ __forceinline__ void upd_token(
    const float4& kv, const float4& vv,
    const float4 qv[GG], float l[GG], float4 acc[GG])
{
    float sc[GG];
#pragma unroll
    for (int g = 0; g < GG; g++)
        sc[g] = kv.x * qv[g].x + kv.y * qv[g].y + kv.z * qv[g].z + kv.w * qv[g].w;
#pragma unroll
    for (int off = 16; off > 0; off >>= 1) {
#pragma unroll
        for (int g = 0; g < GG; g++)
            sc[g] += __shfl_xor_sync(0xffffffffu, sc[g], off);
    }
#pragma unroll
    for (int g = 0; g < GG; g++) {
        float p = __expf(sc[g]);
        l[g] += p;
        acc[g].x += p * vv.x;
        acc[g].y += p * vv.y;
        acc[g].z += p * vv.z;
        acc[g].w += p * vv.w;
    }
}

__device__ __forceinline__ void cp16(unsigned smem_addr, const float* gptr) {
    asm volatile("cp.async.cg.shared.global [%0], [%1], 16;"
                 :: "r"(smem_addr), "l"(gptr));
}

// ---------------- split flash-decode: cp.async double-buffered tiles ----------------
__global__ __launch_bounds__(NTHREADS) void pa_split_kernel(
    const float* __restrict__ value,
    const float* __restrict__ k_cache,
    const float* __restrict__ v_cache,
    const int*   __restrict__ block_table,
    const int*   __restrict__ context_lens)
{
    extern __shared__ float dyn[];
    float* sm_kv   = dyn;                         // [2][KV_TILE][TOKF]
    float* sm_wacc = dyn + 2 * KV_TILE * TOKF;    // [NWARP][GG][DD]
    float* sm_wl   = sm_wacc + NWARP * GG * DD;   // [NWARP][GG]
    int*   btab    = (int*)(sm_wl + NWARP * GG);  // [MAX_BLOCKS]

    const int split = blockIdx.x;
    const int kvh   = blockIdx.y;
    const int b     = blockIdx.z;
    const int tid   = threadIdx.x;
    const int lane  = tid & 31;
    const int w     = tid >> 5;

    const int ctx   = context_lens[b];
    const int chunk = (ctx + NSPLIT - 1) / NSPLIT;
    const int s0    = split * chunk;
    const int s1    = min(s0 + chunk, ctx);
    const int last  = ctx - 1;
    const int end   = min(s1, last);   // hot loop excludes the in-flight token

    for (int i = tid; i < MAX_BLOCKS; i += NTHREADS)
        btab[i] = block_table[b * MAX_BLOCKS + i];
    __syncthreads();

    float4 qv[GG];
#pragma unroll
    for (int g = 0; g < GG; g++)
        qv[g] = *(const float4*)&g_qrot[((long)b * HH + kvh * GG + g) * DD + lane * 4];

    float l[GG];
    float4 acc[GG];
#pragma unroll
    for (int g = 0; g < GG; g++) {
        l[g] = 0.f;
        acc[g].x = acc[g].y = acc[g].z = acc[g].w = 0.f;
    }

    const unsigned hoff = (unsigned)kvh * DD + lane * 4;
#define ROWOFF(t) ((((unsigned)btab[(t) >> 4] * BLK_SZ + ((t) & 15)) * (KVHH * DD)) + hoff)

    const int span  = end - s0;
    const int nfull = span > 0 ? span / KV_TILE : 0;

    // ---- stage helper: warp w stages tokens 4w..4w+3 of tile tt ----
    const unsigned smem_base = (unsigned)__cvta_generic_to_shared(sm_kv);
#define STAGE(tt) do {                                                        \
        int S_ = s0 + (tt) * KV_TILE;                                         \
        int buf_ = (tt) & 1;                                                  \
        _Pragma("unroll")                                                     \
        for (int j_ = 0; j_ < 4; j_++) {                                      \
            int tl_ = w * 4 + j_;                                             \
            unsigned ro_ = ROWOFF(S_ + tl_);                                  \
            unsigned sb_ = smem_base +                                        \
                ((buf_ * KV_TILE + tl_) * TOKF + lane * 4) * 4u;              \
            cp16(sb_,       k_cache + ro_);                                   \
            cp16(sb_ + 512, v_cache + ro_);                                   \
        }                                                                     \
        asm volatile("cp.async.commit_group;");                               \
    } while (0)

    if (nfull > 0) STAGE(0);

    for (int t = 0; t < nfull; t++) {
        if (t + 1 < nfull) {
            STAGE(t + 1);
            asm volatile("cp.async.wait_group 1;");
        } else {
            asm volatile("cp.async.wait_group 0;");
        }
        __syncthreads();

        const float* buf = sm_kv + (t & 1) * KV_TILE * TOKF;
        // warp w computes tokens 4w..4w+3 of this tile from smem
#pragma unroll
        for (int j = 0; j < 4; j++) {
            const float* tok = buf + (w * 4 + j) * TOKF;
            float4 kv = *(const float4*)(tok + lane * 4);
            float4 vv = *(const float4*)(tok + DD + lane * 4);
            upd_token(kv, vv, qv, l, acc);
        }
        __syncthreads();
    }

    // tail: direct-LDG path (R7), tokens s0+nfull*32 .. end-1, warp-interleaved
    int s = s0 + nfull * KV_TILE + w;
    while (s < end) {
        unsigned off = ROWOFF(s);
        float4 kv = *(const float4*)(k_cache + off);
        float4 vv = *(const float4*)(v_cache + off);
        upd_token(kv, vv, qv, l, acc);
        s += NWARP;
    }
#undef ROWOFF
#undef STAGE

    // in-flight token (RoPE'd new k from scratch, new v from input)
    if (last >= s0 && last < s1 && w == ((last - s0) % NWARP)) {
        float4 kv = *(const float4*)&g_krot[((long)b * KVHH + kvh) * DD + lane * 4];
        float4 vv = *(const float4*)(value + ((long)b * KVHH + kvh) * DD + lane * 4);
        upd_token(kv, vv, qv, l, acc);
    }

    // stash per-warp partials (plain sums)
#pragma unroll
    for (int g = 0; g < GG; g++) {
        if (lane == 0) sm_wl[w * GG + g] = l[g];
        *(float4*)&sm_wacc[(w * GG + g) * DD + lane * 4] = acc[g];
    }
    __syncthreads();

    const long pbase = ((long)(b * KVHH + kvh) * NSPLIT + split) * GG;
    for (int i = tid; i < GG * DD; i += NTHREADS) {
        int g = i >> 7, d = i & 127;
        float t = 0.f;
#pragma unroll
        for (int ww = 0; ww < NWARP; ww++) t += sm_wacc[(ww * GG + g) * DD + d];
        g_pacc[(pbase + g) * DD + d] = t;
    }
    if (tid < GG) {
        float L = 0.f;
#pragma unroll
        for (int ww = 0; ww < NWARP; ww++) L += sm_wl[ww * GG + tid];
        g_pl[pbase + tid] = L;
    }
}

// ---------------- combine (plain sums) ----------------
__global__ __launch_bounds__(DD) void pa_combine_kernel(float* __restrict__ out) {
    const int idx = blockIdx.x;             // B*KVH*G
    const int g   = idx % GG;
    const int kvh = (idx / GG) % KVHH;
    const int b   = idx / (GG * KVHH);
    const int d   = threadIdx.x;

    const long base = ((long)(b * KVHH + kvh) * NSPLIT) * GG + g;
    float L = 0.f, o = 0.f;
#pragma unroll
    for (int s = 0; s < NSPLIT; s++) {
        L += g_pl[base + (long)s * GG];
        o += g_pacc[(base + (long)s * GG) * DD + d];
    }
    out[((long)b * HH + kvh * GG + g) * DD + d] = o / L;
}

extern "C" void kernel_launch(void* const* d_in, const int* in_sizes, int n_in,
                              void* d_out, int out_size) {
    const float* query  = (const float*)d_in[0];
    const float* key    = (const float*)d_in[1];
    const float* value  = (const float*)d_in[2];
    const float* k_cache = (const float*)d_in[3];
    const float* v_cache = (const float*)d_in[4];
    const int*   block_table  = (const int*)d_in[5];
    const int*   context_lens = (const int*)d_in[6];
    float* out = (float*)d_out;

    // dynamic smem: 2*32*256 + 8*4*128 + 8*4 floats + 128 ints
    const int smem_bytes = (2 * KV_TILE * TOKF + NWARP * GG * DD + NWARP * GG) * 4
                         + MAX_BLOCKS * 4;
    static bool attr_set = false;
    if (!attr_set) {
        cudaFuncSetAttribute(pa_split_kernel,
                             cudaFuncAttributeMaxDynamicSharedMemorySize, smem_bytes);
        attr_set = true;
    }

    dim3 pgrid(BB, HH + KVHH);
    rope_prep_kernel<<<pgrid, DD>>>(query, key, context_lens);

    dim3 grid(NSPLIT, KVHH, BB);
    pa_split_kernel<<<grid, NTHREADS, smem_bytes>>>(value, k_cache, v_cache,
                                                    block_table, context_lens);
    pa_combine_kernel<<<BB * KVHH * GG, DD>>>(out);
}

// round 14
// speedup vs baseline: 1.4870x; 1.0574x over previous
#include <cuda_runtime.h>
#include <math.h>

#define BB 32
#define HH 32
#define KVHH 8
#define DD 128
#define GG 4
#define BLK_SZ 16
#define MAX_BLOCKS 128
#define NSPLIT 8
#define NWARP 8
#define NTHREADS 256
#define KV_TILE 32      // tokens per stage (CTA-wide); warp owns 4
#define NSTG 3          // pipeline depth
#define TOKB 1024       // bytes per token in smem (K 512 + V 512)

// Scratch (allocation-free: __device__ globals)
__device__ float g_pacc[BB * KVHH * NSPLIT * GG * DD];  // 4 MB split partials
__device__ float g_pl[BB * KVHH * NSPLIT * GG];
__device__ float g_qrot[BB * HH * DD];    // RoPE'd q, scale folded
__device__ float g_krot[BB * KVHH * DD];  // RoPE'd new k

// ---------------- prep: RoPE q and new-k once (R7-proven) ----------------
__global__ __launch_bounds__(DD) void rope_prep_kernel(
    const float* __restrict__ query,
    const float* __restrict__ key,
    const int*   __restrict__ context_lens)
{
    const int b = blockIdx.x;
    const int h = blockIdx.y;
    const int d = threadIdx.x;

    const float pos = (float)context_lens[b];
    const int fi = d & 63;
    const float inv = exp2f(-(float)fi * 0.2076205092783674f);  // log2(10000)/64
    float s, c;
    sincosf(pos * inv, &s, &c);

    if (h < HH) {
        const float* base = query + ((long)b * HH + h) * DD;
        float x = base[d];
        float other = (d < 64) ? -base[d + 64] : base[d - 64];
        g_qrot[((long)b * HH + h) * DD + d] =
            (x * c + other * s) * 0.08838834764831845f;  // D^-0.5
    } else {
        const int kh = h - HH;
        const float* base = key + ((long)b * KVHH + kh) * DD;
        float x = base[d];
        float other = (d < 64) ? -base[d + 64] : base[d - 64];
        g_krot[((long)b * KVHH + kh) * DD + d] = x * c + other * s;
    }
}

// ------- per-token update (R7-proven): no online max, butterfly reduce -------
__device__ __forceinline__ void upd_token(
    const float4& kv, const float4& vv,
    const float4 qv[GG], float l[GG], float4 acc[GG])
{
    float sc[GG];
#pragma unroll
    for (int g = 0; g < GG; g++)
        sc[g] = kv.x * qv[g].x + kv.y * qv[g].y + kv.z * qv[g].z + kv.w * qv[g].w;
#pragma unroll
    for (int off = 16; off > 0; off >>= 1) {
#pragma unroll
        for (int g = 0; g < GG; g++)
            sc[g] += __shfl_xor_sync(0xffffffffu, sc[g], off);
    }
#pragma unroll
    for (int g = 0; g < GG; g++) {
        float p = __expf(sc[g]);
        l[g] += p;
        acc[g].x += p * vv.x;
        acc[g].y += p * vv.y;
        acc[g].z += p * vv.z;
        acc[g].w += p * vv.w;
    }
}

__device__ __forceinline__ void cp16(unsigned smem_addr, const float* gptr) {
    asm volatile("cp.async.cg.shared.global [%0], [%1], 16;"
                 :: "r"(smem_addr), "l"(gptr));
}

// ------- split flash-decode: per-warp cp.async pipeline, barrier-free hot loop -------
__global__ __launch_bounds__(NTHREADS) void pa_split_kernel(
    const float* __restrict__ value,
    const float* __restrict__ k_cache,
    const float* __restrict__ v_cache,
    const int*   __restrict__ block_table,
    const int*   __restrict__ context_lens)
{
    extern __shared__ float dyn[];
    // sm_kv: [warp][stage][4 tokens][256 floats]  (96 KB)
    float* sm_kv = dyn;
    int*   btab  = (int*)(dyn + NWARP * NSTG * 4 * (TOKB / 4));
    // epilogue buffers alias the kv region (used after a barrier)
    float* sm_wacc = dyn;                         // [NWARP][GG][DD]
    float* sm_wl   = dyn + NWARP * GG * DD;       // [NWARP][GG]

    const int split = blockIdx.x;
    const int kvh   = blockIdx.y;
    const int b     = blockIdx.z;
    const int tid   = threadIdx.x;
    const int lane  = tid & 31;
    const int w     = tid >> 5;

    const int ctx   = context_lens[b];
    const int chunk = (ctx + NSPLIT - 1) / NSPLIT;
    const int s0    = split * chunk;
    const int s1    = min(s0 + chunk, ctx);
    const int last  = ctx - 1;
    const int end   = min(s1, last);

    for (int i = tid; i < MAX_BLOCKS; i += NTHREADS)
        btab[i] = block_table[b * MAX_BLOCKS + i];
    __syncthreads();

    float4 qv[GG];
#pragma unroll
    for (int g = 0; g < GG; g++)
        qv[g] = *(const float4*)&g_qrot[((long)b * HH + kvh * GG + g) * DD + lane * 4];

    float l[GG];
    float4 acc[GG];
#pragma unroll
    for (int g = 0; g < GG; g++) {
        l[g] = 0.f;
        acc[g].x = acc[g].y = acc[g].z = acc[g].w = 0.f;
    }

    const unsigned hoff = (unsigned)kvh * DD + lane * 4;
#define ROWOFF(t) ((((unsigned)btab[(t) >> 4] * BLK_SZ + ((t) & 15)) * (KVHH * DD)) + hoff)

    const int span  = end - s0;
    const int nfull = span > 0 ? span / KV_TILE : 0;

    // warp w's smem slice base (bytes): [w][stage][4][1024B]
    const unsigned my_base = (unsigned)__cvta_generic_to_shared(sm_kv)
                           + (unsigned)w * NSTG * 4 * TOKB;
    float* my_buf = sm_kv + (size_t)w * NSTG * 4 * (TOKB / 4);

    // STAGE(tt): warp stages its 4 tokens of tile tt into stage slot tt%NSTG
#define STAGE(tt) do {                                                        \
        int S_ = s0 + (tt) * KV_TILE + w * 4;                                 \
        unsigned sb_ = my_base + (unsigned)((tt) % NSTG) * 4 * TOKB           \
                     + (unsigned)lane * 16;                                   \
        _Pragma("unroll")                                                     \
        for (int j_ = 0; j_ < 4; j_++) {                                      \
            unsigned ro_ = ROWOFF(S_ + j_);                                   \
            cp16(sb_ + j_ * TOKB,       k_cache + ro_);                       \
            cp16(sb_ + j_ * TOKB + 512, v_cache + ro_);                       \
        }                                                                     \
        asm volatile("cp.async.commit_group;");                               \
    } while (0)

    // prologue: fill depth-1 stages
    if (nfull > 0) STAGE(0);
    if (nfull > 1) STAGE(1);

    for (int t = 0; t < nfull; t++) {
        if (t + 2 < nfull) {
            STAGE(t + 2);
            asm volatile("cp.async.wait_group 2;");
        } else if (t + 1 < nfull) {
            asm volatile("cp.async.wait_group 1;");
        } else {
            asm volatile("cp.async.wait_group 0;");
        }
        const float* buf = my_buf + (t % NSTG) * 4 * (TOKB / 4);
#pragma unroll
        for (int j = 0; j < 4; j++) {
            const float* tok = buf + j * (TOKB / 4);
            float4 kv = *(const float4*)(tok + lane * 4);
            float4 vv = *(const float4*)(tok + DD + lane * 4);
            upd_token(kv, vv, qv, l, acc);
        }
    }

    // tail: direct-LDG (R7), tokens s0+nfull*32 .. end-1, warp-interleaved
    int s = s0 + nfull * KV_TILE + w;
    while (s < end) {
        unsigned off = ROWOFF(s);
        float4 kv = *(const float4*)(k_cache + off);
        float4 vv = *(const float4*)(v_cache + off);
        upd_token(kv, vv, qv, l, acc);
        s += NWARP;
    }
#undef ROWOFF
#undef STAGE

    // in-flight token (RoPE'd new k from scratch, new v from input)
    if (last >= s0 && last < s1 && w == ((last - s0) % NWARP)) {
        float4 kv = *(const float4*)&g_krot[((long)b * KVHH + kvh) * DD + lane * 4];
        float4 vv = *(const float4*)(value + ((long)b * KVHH + kvh) * DD + lane * 4);
        upd_token(kv, vv, qv, l, acc);
    }

    // epilogue: alias wacc/wl into the kv region (all kv reads done)
    __syncthreads();
#pragma unroll
    for (int g = 0; g < GG; g++) {
        if (lane == 0) sm_wl[w * GG + g] = l[g];
        *(float4*)&sm_wacc[(w * GG + g) * DD + lane * 4] = acc[g];
    }
    __syncthreads();

    const long pbase = ((long)(b * KVHH + kvh) * NSPLIT + split) * GG;
    for (int i = tid; i < GG * DD; i += NTHREADS) {
        int g = i >> 7, d = i & 127;
        float t = 0.f;
#pragma unroll
        for (int ww = 0; ww < NWARP; ww++) t += sm_wacc[(ww * GG + g) * DD + d];
        g_pacc[(pbase + g) * DD + d] = t;
    }
    if (tid < GG) {
        float L = 0.f;
#pragma unroll
        for (int ww = 0; ww < NWARP; ww++) L += sm_wl[ww * GG + tid];
        g_pl[pbase + tid] = L;
    }
}

// ---------------- combine (plain sums) ----------------
__global__ __launch_bounds__(DD) void pa_combine_kernel(float* __restrict__ out) {
    const int idx = blockIdx.x;             // B*KVH*G
    const int g   = idx % GG;
    const int kvh = (idx / GG) % KVHH;
    const int b   = idx / (GG * KVHH);
    const int d   = threadIdx.x;

    const long base = ((long)(b * KVHH + kvh) * NSPLIT) * GG + g;
    float L = 0.f, o = 0.f;
#pragma unroll
    for (int s = 0; s < NSPLIT; s++) {
        L += g_pl[base + (long)s * GG];
        o += g_pacc[(base + (long)s * GG) * DD + d];
    }
    out[((long)b * HH + kvh * GG + g) * DD + d] = o / L;
}

extern "C" void kernel_launch(void* const* d_in, const int* in_sizes, int n_in,
                              void* d_out, int out_size) {
    const float* query  = (const float*)d_in[0];
    const float* key    = (const float*)d_in[1];
    const float* value  = (const float*)d_in[2];
    const float* k_cache = (const float*)d_in[3];
    const float* v_cache = (const float*)d_in[4];
    const int*   block_table  = (const int*)d_in[5];
    const int*   context_lens = (const int*)d_in[6];
    float* out = (float*)d_out;

    // dynamic smem: kv pipeline (96 KB) + btab
    const int smem_bytes = NWARP * NSTG * 4 * TOKB + MAX_BLOCKS * 4;
    static bool attr_set = false;
    if (!attr_set) {
        cudaFuncSetAttribute(pa_split_kernel,
                             cudaFuncAttributeMaxDynamicSharedMemorySize, smem_bytes);
        attr_set = true;
    }

    dim3 pgrid(BB, HH + KVHH);
    rope_prep_kernel<<<pgrid, DD>>>(query, key, context_lens);

    dim3 grid(NSPLIT, KVHH, BB);
    pa_split_kernel<<<grid, NTHREADS, smem_bytes>>>(value, k_cache, v_cache,
                                                    block_table, context_lens);
    pa_combine_kernel<<<BB * KVHH * GG, DD>>>(out);
}

// round 15
// speedup vs baseline: 1.5914x; 1.0702x over previous
#include <cuda_runtime.h>
#include <math.h>

#define BB 32
#define HH 32
#define KVHH 8
#define DD 128
#define GG 4
#define BLK_SZ 16
#define MAX_BLOCKS 128
#define NSPLIT 8
#define NWARP 8
#define NTHREADS 256
#define NTOK 2          // tokens per warp per stage
#define KV_TILE (NWARP * NTOK)   // 16 tokens per CTA stage
#define NSTG 6          // pipeline depth (prefetch distance 5)
#define TOKB 1024       // bytes per token in smem (K 512 + V 512)

// Scratch (allocation-free: __device__ globals)
__device__ float g_pacc[BB * KVHH * NSPLIT * GG * DD];  // 4 MB split partials
__device__ float g_pl[BB * KVHH * NSPLIT * GG];
__device__ float g_qrot[BB * HH * DD];    // RoPE'd q, scale folded
__device__ float g_krot[BB * KVHH * DD];  // RoPE'd new k

// ---------------- prep: RoPE q and new-k once (R7-proven) ----------------
__global__ __launch_bounds__(DD) void rope_prep_kernel(
    const float* __restrict__ query,
    const float* __restrict__ key,
    const int*   __restrict__ context_lens)
{
    const int b = blockIdx.x;
    const int h = blockIdx.y;
    const int d = threadIdx.x;

    const float pos = (float)context_lens[b];
    const int fi = d & 63;
    const float inv = exp2f(-(float)fi * 0.2076205092783674f);  // log2(10000)/64
    float s, c;
    sincosf(pos * inv, &s, &c);

    if (h < HH) {
        const float* base = query + ((long)b * HH + h) * DD;
        float x = base[d];
        float other = (d < 64) ? -base[d + 64] : base[d - 64];
        g_qrot[((long)b * HH + h) * DD + d] =
            (x * c + other * s) * 0.08838834764831845f;  // D^-0.5
    } else {
        const int kh = h - HH;
        const float* base = key + ((long)b * KVHH + kh) * DD;
        float x = base[d];
        float other = (d < 64) ? -base[d + 64] : base[d - 64];
        g_krot[((long)b * KVHH + kh) * DD + d] = x * c + other * s;
    }
}

// ------- per-token update (R7-proven): no online max, butterfly reduce -------
__device__ __forceinline__ void upd_token(
    const float4& kv, const float4& vv,
    const float4 qv[GG], float l[GG], float4 acc[GG])
{
    float sc[GG];
#pragma unroll
    for (int g = 0; g < GG; g++)
        sc[g] = kv.x * qv[g].x + kv.y * qv[g].y + kv.z * qv[g].z + kv.w * qv[g].w;
#pragma unroll
    for (int off = 16; off > 0; off >>= 1) {
#pragma unroll
        for (int g = 0; g < GG; g++)
            sc[g] += __shfl_xor_sync(0xffffffffu, sc[g], off);
    }
#pragma unroll
    for (int g = 0; g < GG; g++) {
        float p = __expf(sc[g]);
        l[g] += p;
        acc[g].x += p * vv.x;
        acc[g].y += p * vv.y;
        acc[g].z += p * vv.z;
        acc[g].w += p * vv.w;
    }
}

__device__ __forceinline__ void cp16(unsigned smem_addr, const float* gptr) {
    asm volatile("cp.async.cg.shared.global [%0], [%1], 16;"
                 :: "r"(smem_addr), "l"(gptr));
}

// ------- split flash-decode: per-warp 6-deep cp.async pipeline -------
__global__ __launch_bounds__(NTHREADS) void pa_split_kernel(
    const float* __restrict__ value,
    const float* __restrict__ k_cache,
    const float* __restrict__ v_cache,
    const int*   __restrict__ block_table,
    const int*   __restrict__ context_lens)
{
    extern __shared__ float dyn[];
    // sm_kv: [warp][stage][NTOK tokens][256 floats]  (96 KB)
    float* sm_kv = dyn;
    int*   btab  = (int*)(dyn + NWARP * NSTG * NTOK * (TOKB / 4));
    // epilogue buffers alias the kv region (used after a barrier)
    float* sm_wacc = dyn;                         // [NWARP][GG][DD]
    float* sm_wl   = dyn + NWARP * GG * DD;       // [NWARP][GG]

    const int split = blockIdx.x;
    const int kvh   = blockIdx.y;
    const int b     = blockIdx.z;
    const int tid   = threadIdx.x;
    const int lane  = tid & 31;
    const int w     = tid >> 5;

    const int ctx   = context_lens[b];
    const int chunk = (ctx + NSPLIT - 1) / NSPLIT;
    const int s0    = split * chunk;
    const int s1    = min(s0 + chunk, ctx);
    const int last  = ctx - 1;
    const int end   = min(s1, last);

    for (int i = tid; i < MAX_BLOCKS; i += NTHREADS)
        btab[i] = block_table[b * MAX_BLOCKS + i];
    __syncthreads();

    float4 qv[GG];
#pragma unroll
    for (int g = 0; g < GG; g++)
        qv[g] = *(const float4*)&g_qrot[((long)b * HH + kvh * GG + g) * DD + lane * 4];

    float l[GG];
    float4 acc[GG];
#pragma unroll
    for (int g = 0; g < GG; g++) {
        l[g] = 0.f;
        acc[g].x = acc[g].y = acc[g].z = acc[g].w = 0.f;
    }

    const unsigned hoff = (unsigned)kvh * DD + lane * 4;
#define ROWOFF(t) ((((unsigned)btab[(t) >> 4] * BLK_SZ + ((t) & 15)) * (KVHH * DD)) + hoff)

    const int span  = end - s0;
    const int nfull = span > 0 ? span / KV_TILE : 0;

    // warp w's smem slice base (bytes): [w][stage][NTOK][1024B]
    const unsigned my_base = (unsigned)__cvta_generic_to_shared(sm_kv)
                           + (unsigned)w * NSTG * NTOK * TOKB;
    float* my_buf = sm_kv + (size_t)w * NSTG * NTOK * (TOKB / 4);

    // STAGE(tt): warp stages its NTOK tokens of tile tt into slot tt%NSTG
#define STAGE(tt) do {                                                        \
        int S_ = s0 + (tt) * KV_TILE + w * NTOK;                              \
        unsigned sb_ = my_base + (unsigned)((tt) % NSTG) * NTOK * TOKB        \
                     + (unsigned)lane * 16;                                   \
        _Pragma("unroll")                                                     \
        for (int j_ = 0; j_ < NTOK; j_++) {                                   \
            unsigned ro_ = ROWOFF(S_ + j_);                                   \
            cp16(sb_ + j_ * TOKB,       k_cache + ro_);                       \
            cp16(sb_ + j_ * TOKB + 512, v_cache + ro_);                       \
        }                                                                     \
        asm volatile("cp.async.commit_group;");                               \
    } while (0)
#define STAGE_OR_EMPTY(tt) do {                                               \
        if ((tt) < nfull) STAGE(tt);                                          \
        else asm volatile("cp.async.commit_group;");                          \
    } while (0)

    // prologue: 5 commits (real or empty) -> constant wait depth in the loop
    STAGE_OR_EMPTY(0);
    STAGE_OR_EMPTY(1);
    STAGE_OR_EMPTY(2);
    STAGE_OR_EMPTY(3);
    STAGE_OR_EMPTY(4);

    for (int t = 0; t < nfull; t++) {
        STAGE_OR_EMPTY(t + 5);
        asm volatile("cp.async.wait_group 5;");
        const float* buf = my_buf + (t % NSTG) * NTOK * (TOKB / 4);
#pragma unroll
        for (int j = 0; j < NTOK; j++) {
            const float* tok = buf + j * (TOKB / 4);
            float4 kv = *(const float4*)(tok + lane * 4);
            float4 vv = *(const float4*)(tok + DD + lane * 4);
            upd_token(kv, vv, qv, l, acc);
        }
    }

    // tail: direct-LDG (R7), tokens s0+nfull*16 .. end-1, warp-interleaved
    int s = s0 + nfull * KV_TILE + w;
    while (s < end) {
        unsigned off = ROWOFF(s);
        float4 kv = *(const float4*)(k_cache + off);
        float4 vv = *(const float4*)(v_cache + off);
        upd_token(kv, vv, qv, l, acc);
        s += NWARP;
    }
#undef ROWOFF
#undef STAGE
#undef STAGE_OR_EMPTY

    // in-flight token (RoPE'd new k from scratch, new v from input)
    if (last >= s0 && last < s1 && w == ((last - s0) % NWARP)) {
        float4 kv = *(const float4*)&g_krot[((long)b * KVHH + kvh) * DD + lane * 4];
        float4 vv = *(const float4*)(value + ((long)b * KVHH + kvh) * DD + lane * 4);
        upd_token(kv, vv, qv, l, acc);
    }

    // epilogue: alias wacc/wl into the kv region (all kv reads done)
    __syncthreads();
#pragma unroll
    for (int g = 0; g < GG; g++) {
        if (lane == 0) sm_wl[w * GG + g] = l[g];
        *(float4*)&sm_wacc[(w * GG + g) * DD + lane * 4] = acc[g];
    }
    __syncthreads();

    const long pbase = ((long)(b * KVHH + kvh) * NSPLIT + split) * GG;
    for (int i = tid; i < GG * DD; i += NTHREADS) {
        int g = i >> 7, d = i & 127;
        float t = 0.f;
#pragma unroll
        for (int ww = 0; ww < NWARP; ww++) t += sm_wacc[(ww * GG + g) * DD + d];
        g_pacc[(pbase + g) * DD + d] = t;
    }
    if (tid < GG) {
        float L = 0.f;
#pragma unroll
        for (int ww = 0; ww < NWARP; ww++) L += sm_wl[ww * GG + tid];
        g_pl[pbase + tid] = L;
    }
}

// ---------------- combine (plain sums) ----------------
__global__ __launch_bounds__(DD) void pa_combine_kernel(float* __restrict__ out) {
    const int idx = blockIdx.x;             // B*KVH*G
    const int g   = idx % GG;
    const int kvh = (idx / GG) % KVHH;
    const int b   = idx / (GG * KVHH);
    const int d   = threadIdx.x;

    const long base = ((long)(b * KVHH + kvh) * NSPLIT) * GG + g;
    float L = 0.f, o = 0.f;
#pragma unroll
    for (int s = 0; s < NSPLIT; s++) {
        L += g_pl[base + (long)s * GG];
        o += g_pacc[(base + (long)s * GG) * DD + d];
    }
    out[((long)b * HH + kvh * GG + g) * DD + d] = o / L;
}

extern "C" void kernel_launch(void* const* d_in, const int* in_sizes, int n_in,
                              void* d_out, int out_size) {
    const float* query  = (const float*)d_in[0];
    const float* key    = (const float*)d_in[1];
    const float* value  = (const float*)d_in[2];
    const float* k_cache = (const float*)d_in[3];
    const float* v_cache = (const float*)d_in[4];
    const int*   block_table  = (const int*)d_in[5];
    const int*   context_lens = (const int*)d_in[6];
    float* out = (float*)d_out;

    // dynamic smem: kv pipeline (96 KB) + btab
    const int smem_bytes = NWARP * NSTG * NTOK * TOKB + MAX_BLOCKS * 4;
    static bool attr_set = false;
    if (!attr_set) {
        cudaFuncSetAttribute(pa_split_kernel,
                             cudaFuncAttributeMaxDynamicSharedMemorySize, smem_bytes);
        attr_set = true;
    }

    dim3 pgrid(BB, HH + KVHH);
    rope_prep_kernel<<<pgrid, DD>>>(query, key, context_lens);

    dim3 grid(NSPLIT, KVHH, BB);
    pa_split_kernel<<<grid, NTHREADS, smem_bytes>>>(value, k_cache, v_cache,
                                                    block_table, context_lens);
    pa_combine_kernel<<<BB * KVHH * GG, DD>>>(out);
}